// round 2
// baseline (speedup 1.0000x reference)
#include <cuda_runtime.h>

#define T_TOTAL 131072
#define FEAT    8
#define HIDDEN  256
#define MAXK    10
#define BUF     50
#define NM1     49          // nm1 for a full window
#define BLK     256

// Compile-time-foldable normalization coefficient for full windows:
// coef(k,m) = nm1 / (len * k) / k  with len = (nm1-m)/k + 1
__device__ __forceinline__ float coef_full(int k, int m) {
    int len = (NM1 - m) / k + 1;
    return (float)NM1 / ((float)len * (float)(k * k));
}

__constant__ float c_logk[MAXK + 1] = {
    0.0f,
    0.0f, 0.69314718056f, 1.09861228867f, 1.38629436112f, 1.60943791243f,
    1.79175946923f, 1.94591014906f, 2.07944154168f, 2.19722457734f, 2.30258509299f
};

__global__ __launch_bounds__(BLK)
void hfd_fused_kernel(const float* __restrict__ x,
                      const float* __restrict__ wlin,
                      const float* __restrict__ blin,
                      float* __restrict__ out)
{
    __shared__ float s[BLK + BUF - 1];   // 305 staged prices
    __shared__ float hfd_s[BLK];

    const int tid = threadIdx.x;
    const int B   = blockIdx.x * BLK;

    // Stage prices p[B-49 .. B+255] (column 3 of x), clamped at 0 for block 0.
    for (int i = tid; i < BLK + BUF - 1; i += BLK) {
        int gi = B - (BUF - 1) + i;
        gi = gi < 0 ? 0 : gi;
        s[i] = x[gi * FEAT + 3];
    }
    __syncthreads();

    const int t = B + tid;
    float hfd = 0.0f;

    if (t >= BUF - 1) {
        // ---- fast path: full window, all coefficients compile-time constants ----
        float w[BUF];
        #pragma unroll
        for (int j = 0; j < BUF; j++) w[j] = s[tid + j];

        float cc = 0.f, sx = 0.f, sy = 0.f, sxy = 0.f, sxx = 0.f;
        #pragma unroll
        for (int k = 1; k <= MAXK; k++) {
            float Lk = 0.f;
            #pragma unroll
            for (int q = 0; q + k <= NM1; q++) {
                float d = w[q + k] - w[q];
                Lk += fabsf(d) * coef_full(k, q % k);
            }
            if (Lk > 0.f) {
                float lx = c_logk[k];
                float ly = logf(Lk);
                cc += 1.f; sx += lx; sy += ly;
                sxy += ly * lx; sxx += lx * lx;
            }
        }
        float denom = cc * sxx - sx * sx;
        if (denom == 0.f) denom = 1.f;
        float slope = (cc * sxy - sx * sy) / denom;
        hfd = (cc > 1.f) ? -slope : 0.f;       // n = 50 >= 11 guaranteed here
    } else if (t >= MAXK) {
        // ---- slow path: partial window (t in [10,48]) — 39 threads total ----
        const int nm1 = t;                      // start = 0, window = p[0..t]
        const float nm1f = (float)nm1;
        float cc = 0.f, sx = 0.f, sy = 0.f, sxy = 0.f, sxx = 0.f;
        for (int k = 1; k <= MAXK; k++) {
            float acc = 0.f;
            for (int m = 0; m < k; m++) {
                int len = (nm1 >= m) ? (nm1 - m) / k + 1 : 0;
                if (len >= 2) {
                    float S = 0.f;
                    for (int q = m; q + k <= nm1; q += k)
                        S += fabsf(x[(q + k) * FEAT + 3] - x[q * FEAT + 3]);
                    acc += S * nm1f / ((float)len * (float)k);
                }
            }
            float Lk = acc / (float)k;
            if (Lk > 0.f) {
                float lx = c_logk[k];
                float ly = logf(Lk);
                cc += 1.f; sx += lx; sy += ly;
                sxy += ly * lx; sxx += lx * lx;
            }
        }
        float denom = cc * sxx - sx * sx;
        if (denom == 0.f) denom = 1.f;
        float slope = (cc * sxy - sx * sy) / denom;
        hfd = (cc > 1.f) ? -slope : 0.f;        // n = t+1 >= 11 since t >= 10
    }
    // t < 10: hfd stays 0

    hfd_s[tid] = hfd;
    __syncthreads();

    // ---- epilogue: out[B+r][h] = relu(hfd[B+r] * w[h] + b[h]), float4 stores ----
    const int c4 = tid & 63;                    // float4 column group (4 cols)
    const int r0 = tid >> 6;                    // starting row within tile
    const float4 w4 = reinterpret_cast<const float4*>(wlin)[c4];
    const float4 b4 = reinterpret_cast<const float4*>(blin)[c4];

    float4* __restrict__ out4 = reinterpret_cast<float4*>(out);

    #pragma unroll 16
    for (int r = r0; r < BLK; r += 4) {
        float h = hfd_s[r];
        float4 o;
        o.x = fmaxf(fmaf(h, w4.x, b4.x), 0.f);
        o.y = fmaxf(fmaf(h, w4.y, b4.y), 0.f);
        o.z = fmaxf(fmaf(h, w4.z, b4.z), 0.f);
        o.w = fmaxf(fmaf(h, w4.w, b4.w), 0.f);
        out4[(size_t)(B + r) * (HIDDEN / 4) + c4] = o;
    }
}

extern "C" void kernel_launch(void* const* d_in, const int* in_sizes, int n_in,
                              void* d_out, int out_size)
{
    const float* x    = (const float*)d_in[0];   // [T, 8]
    const float* wlin = (const float*)d_in[1];   // [256, 1]
    const float* blin = (const float*)d_in[2];   // [256]
    float* out = (float*)d_out;                  // [T, 256]

    hfd_fused_kernel<<<T_TOTAL / BLK, BLK>>>(x, wlin, blin, out);
}

// round 3
// speedup vs baseline: 1.0310x; 1.0310x over previous
#include <cuda_runtime.h>

#define T_TOTAL 131072
#define FEAT    8
#define HIDDEN  256
#define MAXK    10
#define BUF     50
#define NM1     49          // nm1 for a full window
#define BLK     256

__device__ float g_hfd[T_TOTAL];   // intermediate HFD values (0.5 MB, L2-resident)

// Compile-time-foldable normalization coefficient for full windows:
// coef(k,m) = nm1 / (len * k) / k  with len = (nm1-m)/k + 1
__device__ __forceinline__ float coef_full(int k, int m) {
    int len = (NM1 - m) / k + 1;
    return (float)NM1 / ((float)len * (float)(k * k));
}

__constant__ float c_logk[MAXK + 1] = {
    0.0f,
    0.0f, 0.69314718056f, 1.09861228867f, 1.38629436112f, 1.60943791243f,
    1.79175946923f, 1.94591014906f, 2.07944154168f, 2.19722457734f, 2.30258509299f
};

// ---------------------------------------------------------------------------
// Kernel 1: HFD per timestep. Latency-optimized: 4 independent accumulators
// break the dependent FFMA chain; all normalization coefficients are
// compile-time immediates on the full-window path.
// ---------------------------------------------------------------------------
__global__ __launch_bounds__(BLK)
void hfd_compute_kernel(const float* __restrict__ x)
{
    __shared__ float s[BLK + BUF - 1];   // 305 staged prices

    const int tid = threadIdx.x;
    const int B   = blockIdx.x * BLK;

    // Stage prices p[B-49 .. B+255] (column 3 of x), clamped at 0 for block 0.
    for (int i = tid; i < BLK + BUF - 1; i += BLK) {
        int gi = B - (BUF - 1) + i;
        gi = gi < 0 ? 0 : gi;
        s[i] = x[gi * FEAT + 3];
    }
    __syncthreads();

    const int t = B + tid;
    float hfd = 0.0f;

    if (t >= BUF - 1) {
        // ---- fast path: full window ----
        float w[BUF];
        #pragma unroll
        for (int j = 0; j < BUF; j++) w[j] = s[tid + j];

        float cc = 0.f, sx = 0.f, sy = 0.f, sxy = 0.f, sxx = 0.f;
        #pragma unroll
        for (int k = 1; k <= MAXK; k++) {
            // 4 independent partial sums -> 4x shorter dependency chain
            float a0 = 0.f, a1 = 0.f, a2 = 0.f, a3 = 0.f;
            #pragma unroll
            for (int q = 0; q + k <= NM1; q += 4) {
                a0 += fabsf(w[q + k] - w[q]) * coef_full(k, q % k);
                if (q + 1 + k <= NM1)
                    a1 += fabsf(w[q + 1 + k] - w[q + 1]) * coef_full(k, (q + 1) % k);
                if (q + 2 + k <= NM1)
                    a2 += fabsf(w[q + 2 + k] - w[q + 2]) * coef_full(k, (q + 2) % k);
                if (q + 3 + k <= NM1)
                    a3 += fabsf(w[q + 3 + k] - w[q + 3]) * coef_full(k, (q + 3) % k);
            }
            float Lk = (a0 + a1) + (a2 + a3);
            if (Lk > 0.f) {
                float lx = c_logk[k];
                float ly = logf(Lk);
                cc += 1.f; sx += lx; sy += ly;
                sxy += ly * lx; sxx += lx * lx;
            }
        }
        float denom = cc * sxx - sx * sx;
        if (denom == 0.f) denom = 1.f;
        float slope = (cc * sxy - sx * sy) / denom;
        hfd = (cc > 1.f) ? -slope : 0.f;       // n = 50 >= 11 guaranteed
    } else if (t >= MAXK) {
        // ---- slow path: partial window (t in [10,48]) — 39 threads total ----
        const int nm1 = t;                      // window = p[0..t]
        const float nm1f = (float)nm1;
        float cc = 0.f, sx = 0.f, sy = 0.f, sxy = 0.f, sxx = 0.f;
        for (int k = 1; k <= MAXK; k++) {
            float acc = 0.f;
            for (int m = 0; m < k; m++) {
                int len = (nm1 >= m) ? (nm1 - m) / k + 1 : 0;
                if (len >= 2) {
                    float S = 0.f;
                    for (int q = m; q + k <= nm1; q += k)
                        S += fabsf(x[(q + k) * FEAT + 3] - x[q * FEAT + 3]);
                    acc += S * nm1f / ((float)len * (float)k);
                }
            }
            float Lk = acc / (float)k;
            if (Lk > 0.f) {
                float lx = c_logk[k];
                float ly = logf(Lk);
                cc += 1.f; sx += lx; sy += ly;
                sxy += ly * lx; sxx += lx * lx;
            }
        }
        float denom = cc * sxx - sx * sx;
        if (denom == 0.f) denom = 1.f;
        float slope = (cc * sxy - sx * sy) / denom;
        hfd = (cc > 1.f) ? -slope : 0.f;        // n = t+1 >= 11 since t >= 10
    }
    // t < 10: hfd stays 0

    g_hfd[t] = hfd;
}

// ---------------------------------------------------------------------------
// Kernel 2: streaming epilogue. out[t][h] = relu(hfd[t]*w[h] + b[h]).
// Pure bandwidth: grid-stride float4 stores with streaming cache hint,
// hfd/w/b reads all cache-resident.
// ---------------------------------------------------------------------------
#define EPI_BLK   256
#define EPI_GRID  4096
#define TOTAL4    (T_TOTAL * (HIDDEN / 4))     // 8,388,608 float4 stores

__global__ __launch_bounds__(EPI_BLK)
void epilogue_kernel(const float* __restrict__ wlin,
                     const float* __restrict__ blin,
                     float4* __restrict__ out4)
{
    const float4* __restrict__ w4p = reinterpret_cast<const float4*>(wlin);
    const float4* __restrict__ b4p = reinterpret_cast<const float4*>(blin);

    int pos = blockIdx.x * EPI_BLK + threadIdx.x;
    const int stride = EPI_BLK * EPI_GRID;

    #pragma unroll
    for (int i = 0; i < TOTAL4 / (EPI_BLK * EPI_GRID); i++, pos += stride) {
        const int row = pos >> 6;          // HIDDEN/4 = 64 float4 per row
        const int col = pos & 63;
        const float h  = __ldg(&g_hfd[row]);
        const float4 w4 = __ldg(&w4p[col]);
        const float4 b4 = __ldg(&b4p[col]);
        float4 o;
        o.x = fmaxf(fmaf(h, w4.x, b4.x), 0.f);
        o.y = fmaxf(fmaf(h, w4.y, b4.y), 0.f);
        o.z = fmaxf(fmaf(h, w4.z, b4.z), 0.f);
        o.w = fmaxf(fmaf(h, w4.w, b4.w), 0.f);
        __stcs(&out4[pos], o);             // streaming store: bypass L2 persistence
    }
}

extern "C" void kernel_launch(void* const* d_in, const int* in_sizes, int n_in,
                              void* d_out, int out_size)
{
    const float* x    = (const float*)d_in[0];   // [T, 8]
    const float* wlin = (const float*)d_in[1];   // [256, 1]
    const float* blin = (const float*)d_in[2];   // [256]
    float4* out4 = (float4*)d_out;               // [T, 256]

    hfd_compute_kernel<<<T_TOTAL / BLK, BLK>>>(x);
    epilogue_kernel<<<EPI_GRID, EPI_BLK>>>(wlin, blin, out4);
}